// round 11
// baseline (speedup 1.0000x reference)
#include <cuda_runtime.h>
#include <cstdint>

#define BB 16
#define DD 512
#define TT 4096

// recurrence: 16 clusters (=batches) x 4 CTAs (=128-col slices) x 256 threads
#define CLU 4
#define TPC 256
#define CPC 128
// smem layout (float offsets)
#define REDA_OFF 0
#define REDB_OFF 128
#define MBAR_OFF 256                       // 8 bytes
#define FEAT_OFF 260                       // [2][512] (1040B -> 16B aligned)
#define WT_OFF   (FEAT_OFF + 2 * DD)       // 1284 (5136B, 16B aligned)
#define WT_STRIDE 68                       // 17 float4: conflict-free LDS.128
#define SMEM_REC_FLOATS (WT_OFF + 256 * WT_STRIDE)
#define SMEM_REC_BYTES (SMEM_REC_FLOATS * 4)

// resbuf[b][i][t]  (128 MB) static scratch
__device__ float g_resbuf[(size_t)BB * DD * TT];

__device__ __forceinline__ uint32_t smem_u32(const void* p) {
    uint32_t a;
    asm("{ .reg .u64 t; cvta.to.shared.u64 t, %1; cvt.u32.u64 %0, t; }" : "=r"(a) : "l"(p));
    return a;
}
__device__ __forceinline__ void st_cluster_f32(uint32_t addr, uint32_t rank, float v) {
    asm volatile("{ .reg .u32 r; mapa.shared::cluster.u32 r, %0, %1; st.shared::cluster.f32 [r], %2; }"
                 :: "r"(addr), "r"(rank), "f"(v) : "memory");
}
__device__ __forceinline__ void mbar_init(uint32_t addr, uint32_t cnt) {
    asm volatile("mbarrier.init.shared.b64 [%0], %1;" :: "r"(addr), "r"(cnt) : "memory");
}
__device__ __forceinline__ void mbar_arrive_remote(uint32_t local_addr, uint32_t rank) {
    asm volatile(
        "{ .reg .u32 r; mapa.shared::cluster.u32 r, %0, %1; "
        "mbarrier.arrive.release.cluster.shared::cluster.b64 _, [r]; }"
        :: "r"(local_addr), "r"(rank) : "memory");
}
__device__ __forceinline__ void mbar_wait_parity(uint32_t addr, uint32_t parity) {
    asm volatile(
        "{ .reg .pred P;\n\t"
        "WL_%=: mbarrier.try_wait.parity.acquire.cluster.shared::cta.b64 P, [%0], %1, 0x989680;\n\t"
        "@P bra WD_%=;\n\t"
        "bra WL_%=;\n\t"
        "WD_%=: }"
        :: "r"(addr), "r"(parity) : "memory");
}
__device__ __forceinline__ void cluster_sync_() {
    asm volatile("barrier.cluster.arrive.aligned;" ::: "memory");
    asm volatile("barrier.cluster.wait.aligned;" ::: "memory");
}

// ============================================================================
// Recurrence body, ordering "C" (bit-exact, verified rounds 5-10):
// per element: h0 = fma-chain k=0..255 (single fp32 acc, ascending k),
//              h1 = fma-chain k=256..511, s = h0 + h1, v = clip(4*(s+x)).
//
// Compute config = R9 (best): 4 CTAs x 256 threads, W 3/4 in regs, feat
// broadcast LDS (warp-uniform address), SMEM reduce for the half-combine.
// Sync (new): per-CTA mbarrier, 4 aggregated arrivals per phase.
//   pushes -> __syncthreads (HB edge) -> tid 128..131 send ONE remote
//   release-arrive each -> consumers try_wait.parity.acquire (~60-90 cyc
//   wake vs ~490 for barrier.cluster.wait).
// ============================================================================
template <int NSTEPS>
__device__ __forceinline__ void rec_body(const float* __restrict__ x,
                                         const float* __restrict__ W) {
    extern __shared__ float sm[];
    float* redA  = sm + REDA_OFF;    // [128] h0 partials
    float* redB  = sm + REDB_OFF;    // [128] h1 partials
    float* feats = sm + FEAT_OFF;    // [2][512]
    float* Wt    = sm + WT_OFF;      // [256][68]

    const int tid  = threadIdx.x;
    const int rank = blockIdx.x & 3;
    const int b    = blockIdx.x >> 2;
    const int col  = tid & 127;
    const int h    = tid >> 7;        // 0 or 1 (which 256-half)
    const int j0   = rank * CPC;
    const int gj   = j0 + col;

    const uint32_t sm_u32    = smem_u32(sm);
    const uint32_t mbar_addr = sm_u32 + MBAR_OFF * 4;
    const uint32_t feats_u32 = sm_u32 + FEAT_OFF * 4;

    if (tid == 0) mbar_init(mbar_addr, 4);   // 4 producer CTAs per phase

    // SMEM quarter (groups g=4q+3 of both halves), coalesced over columns
    for (int e = tid; e < 256 * 64; e += TPC) {
        int colr = e & 127;
        int j    = (e >> 7) & 3;
        int q    = (e >> 9) & 15;
        int hr   = e >> 13;
        int k    = hr * 256 + 16 * q + 12 + j;
        Wt[(hr * 128 + colr) * WT_STRIDE + q * 4 + j] =
            W[(size_t)k * DD + j0 + colr];
    }
    for (int e = tid; e < 2 * DD; e += TPC) feats[e] = 0.f;

    // Register-pinned 3/4: own half, groups g=4q+m (m=0..2)
    float wreg[192];
#pragma unroll
    for (int q = 0; q < 16; q++)
#pragma unroll
        for (int m = 0; m < 3; m++)
#pragma unroll
            for (int j = 0; j < 4; j++) {
                int k = h * 256 + 16 * q + 4 * m + j;
                wreg[(q * 3 + m) * 4 + j] = W[(size_t)k * DD + gj];
            }

    const float4* __restrict__ wq4 =
        (const float4*)(Wt + (h * 128 + col) * WT_STRIDE);   // 16 groups
    const float* __restrict__ xp = x + ((size_t)b * DD + gj) * TT;
    float* __restrict__ rp = g_resbuf + ((size_t)b * DD + gj) * TT;

    float xv_next = __ldg(xp);    // x for t=0

    __syncthreads();
    cluster_sync_();              // mbar init + feats zero visible cluster-wide

    for (int t = 0; t < NSTEPS; t++) {
        // wait for all 4 producer-CTA arrivals of phase t-1
        if (t) mbar_wait_parity(mbar_addr, (t - 1) & 1);
        const float xv = xv_next;

        // 256-long single-accumulator fma chain, ascending k (own half).
        const float4* __restrict__ f4 =
            (const float4*)(feats + (t & 1) * DD) + h * 64;
        float a = 0.f;
#pragma unroll
        for (int q = 0; q < 16; q++) {
#pragma unroll
            for (int m = 0; m < 3; m++) {
                const float4 f = f4[4 * q + m];
                const int wb = (q * 3 + m) * 4;
                a = fmaf(f.x, wreg[wb + 0], a);
                a = fmaf(f.y, wreg[wb + 1], a);
                a = fmaf(f.z, wreg[wb + 2], a);
                a = fmaf(f.w, wreg[wb + 3], a);
            }
            const float4 f = f4[4 * q + 3];
            const float4 w = wq4[q];
            a = fmaf(f.x, w.x, a);
            a = fmaf(f.y, w.y, a);
            a = fmaf(f.z, w.z, a);
            a = fmaf(f.w, w.w, a);
        }

        if (h == 0) redA[col] = a; else redB[col] = a;
        __syncthreads();

        const float s = redA[col] + redB[col];       // h0 + h1 (exact order)
        const float v = fminf(1.f, fmaxf(-1.f, 4.f * (s + xv)));

        if (t < NSTEPS - 1) {
            // broadcast to this half's two ranks
            const uint32_t dst =
                feats_u32 + (uint32_t)((((t & 1) ^ 1)) * DD + gj) * 4u;
            st_cluster_f32(dst, (uint32_t)(2 * h), v);
            st_cluster_f32(dst, (uint32_t)(2 * h + 1), v);
            __syncthreads();   // HB edge: all pushes precede the arrives
            if ((tid & ~3) == 128) {
                // one release-arrive per destination rank (4 total per CTA)
                mbar_arrive_remote(mbar_addr, (uint32_t)(tid - 128));
            }
            // overlap window: non-critical work while arrivals are in flight
            if (h == 0) rp[t] = v;
            xv_next = __ldg(xp + t + 1);
        } else {
            if (h == 0) rp[t] = v;
        }
    }
    cluster_sync_();   // keep SMEM/mbar alive until all ranks are done
}

__global__ void __cluster_dims__(CLU, 1, 1) __launch_bounds__(TPC, 1)
rec_kernel(const float* __restrict__ x, const float* __restrict__ W) {
    rec_body<TT>(x, W);
}

// probe clone (also shifts ncu's capture slot onto the full rec_kernel)
__global__ void __cluster_dims__(CLU, 1, 1) __launch_bounds__(TPC, 1)
rec_probe_kernel(const float* __restrict__ x, const float* __restrict__ W) {
    rec_body<12>(x, W);
}

// ============================================================================
// Projection: out[b][o][t] = sum_i lin_w[o][i] * resbuf[b][i][t] + lin_b[o]
// 128x128 tile, 8x8 microtile, packed fma.rn.f32x2 (FFMA2).
// ============================================================================
typedef unsigned long long u64;
#define FMA2(d, a, bv) \
    asm("fma.rn.f32x2 %0, %1, %2, %0;" : "+l"(d) : "l"(a), "l"(bv))
#define PACK2(o, lo, hi) \
    asm("mov.b64 %0, {%1, %2};" : "=l"(o) : "f"(lo), "f"(hi))
#define UNPACK2(lo, hi, v) \
    asm("mov.b64 {%0, %1}, %2;" : "=f"(lo), "=f"(hi) : "l"(v))

__global__ void __launch_bounds__(256) proj_kernel(
    const float* __restrict__ lin_w, const float* __restrict__ lin_b,
    float* __restrict__ out) {

    const float* rb = g_resbuf;
    const int b  = blockIdx.z;
    const int o0 = blockIdx.y * 128;
    const int t0 = blockIdx.x * 128;

    __shared__ float As[8][128];
    __shared__ float Bs[8][128];

    const int tid = threadIdx.x;
    const int tx  = tid & 15;
    const int ty  = tid >> 4;

    u64 acc2[8][4];
#pragma unroll
    for (int r = 0; r < 8; r++)
#pragma unroll
        for (int c = 0; c < 4; c++) acc2[r][c] = 0ull;

    const int lo   = tid >> 1;
    const int half = (tid & 1) * 4;
    const int brow = tid >> 5;
    const int bc4  = (tid & 31) * 4;

    for (int k0 = 0; k0 < DD; k0 += 8) {
        float4 av = *(const float4*)&lin_w[(size_t)(o0 + lo) * DD + k0 + half];
        float4 bv = *(const float4*)&rb[((size_t)b * DD + k0 + brow) * TT + t0 + bc4];
        __syncthreads();
        As[half + 0][lo] = av.x; As[half + 1][lo] = av.y;
        As[half + 2][lo] = av.z; As[half + 3][lo] = av.w;
        *(float4*)&Bs[brow][bc4] = bv;
        __syncthreads();

#pragma unroll
        for (int ii = 0; ii < 8; ii++) {
            float4 a0 = *(const float4*)&As[ii][ty * 4];
            float4 a1 = *(const float4*)&As[ii][64 + ty * 4];
            float4 b0 = *(const float4*)&Bs[ii][tx * 4];
            float4 b1 = *(const float4*)&Bs[ii][64 + tx * 4];
            u64 b2[4];
            PACK2(b2[0], b0.x, b0.y); PACK2(b2[1], b0.z, b0.w);
            PACK2(b2[2], b1.x, b1.y); PACK2(b2[3], b1.z, b1.w);
            float a[8] = {a0.x, a0.y, a0.z, a0.w, a1.x, a1.y, a1.z, a1.w};
#pragma unroll
            for (int r = 0; r < 8; r++) {
                u64 a2;
                PACK2(a2, a[r], a[r]);
                FMA2(acc2[r][0], a2, b2[0]);
                FMA2(acc2[r][1], a2, b2[1]);
                FMA2(acc2[r][2], a2, b2[2]);
                FMA2(acc2[r][3], a2, b2[3]);
            }
        }
    }

#pragma unroll
    for (int g = 0; g < 2; g++) {
#pragma unroll
        for (int r = 0; r < 4; r++) {
            const int ar = g * 4 + r;
            const int o  = o0 + g * 64 + ty * 4 + r;
            const float bias = lin_b[o];
            float c0, c1, c2, c3, c4, c5, c6, c7;
            UNPACK2(c0, c1, acc2[ar][0]); UNPACK2(c2, c3, acc2[ar][1]);
            UNPACK2(c4, c5, acc2[ar][2]); UNPACK2(c6, c7, acc2[ar][3]);
            float4 v0, v1;
            v0.x = c0 + bias; v0.y = c1 + bias; v0.z = c2 + bias; v0.w = c3 + bias;
            v1.x = c4 + bias; v1.y = c5 + bias; v1.z = c6 + bias; v1.w = c7 + bias;
            float* op = &out[((size_t)b * DD + o) * TT + t0];
            *(float4*)(op + tx * 4)      = v0;
            *(float4*)(op + 64 + tx * 4) = v1;
        }
    }
}

extern "C" void kernel_launch(void* const* d_in, const int* in_sizes, int n_in,
                              void* d_out, int out_size) {
    const float* x     = (const float*)d_in[0];
    const float* W     = (const float*)d_in[1];
    const float* lin_w = (const float*)d_in[2];
    const float* lin_b = (const float*)d_in[3];
    float* out = (float*)d_out;

    cudaFuncSetAttribute(rec_kernel,
                         cudaFuncAttributeMaxDynamicSharedMemorySize,
                         SMEM_REC_BYTES);
    cudaFuncSetAttribute(rec_probe_kernel,
                         cudaFuncAttributeMaxDynamicSharedMemorySize,
                         SMEM_REC_BYTES);

    // order [rec, proj, probe]: ncu's capture slot (#6 overall) lands on the
    // FULL rec_kernel of the 2nd profiled call -> steady-state rec profile.
    rec_kernel<<<dim3(BB * CLU), TPC, SMEM_REC_BYTES>>>(x, W);
    proj_kernel<<<dim3(TT / 128, DD / 128, BB), 256>>>(lin_w, lin_b, out);
    rec_probe_kernel<<<dim3(BB * CLU), TPC, SMEM_REC_BYTES>>>(x, W);
}

// round 12
// speedup vs baseline: 1.0652x; 1.0652x over previous
#include <cuda_runtime.h>
#include <cstdint>

#define BB 16
#define DD 512
#define TT 4096

// recurrence: 16 clusters (=batches) x 4 CTAs (=128-col slices) x 256 threads
// thread tid = 2*col + h : lane pairs (h0,h1) of the same column
#define CLU 4
#define TPC 256
#define CPC 128
// smem layout (float offsets); feat halves padded apart: h1 at +260
#define FBUF 520
#define FEAT_OFF 0                         // [2][520]
#define WT_OFF   (2 * FBUF)                // 1040 (16B aligned)
#define WT_STRIDE 68                       // float4-aligned row stride
#define SMEM_REC_FLOATS (WT_OFF + 256 * WT_STRIDE)
#define SMEM_REC_BYTES (SMEM_REC_FLOATS * 4)

// resbuf[b][i][t]  (128 MB) static scratch
__device__ float g_resbuf[(size_t)BB * DD * TT];

__device__ __forceinline__ uint32_t smem_u32(const void* p) {
    uint32_t a;
    asm("{ .reg .u64 t; cvta.to.shared.u64 t, %1; cvt.u32.u64 %0, t; }" : "=r"(a) : "l"(p));
    return a;
}
__device__ __forceinline__ void st_cluster_f32(uint32_t addr, uint32_t rank, float v) {
    asm volatile("{ .reg .u32 r; mapa.shared::cluster.u32 r, %0, %1; st.shared::cluster.f32 [r], %2; }"
                 :: "r"(addr), "r"(rank), "f"(v) : "memory");
}
__device__ __forceinline__ void cluster_arrive_() {
    asm volatile("barrier.cluster.arrive.aligned;" ::: "memory");
}
__device__ __forceinline__ void cluster_wait_() {
    asm volatile("barrier.cluster.wait.aligned;" ::: "memory");
}
__device__ __forceinline__ void cluster_sync_() {
    cluster_arrive_(); cluster_wait_();
}

// ============================================================================
// Recurrence, ordering "C" (bit-exact, verified rounds 5-11):
// per element: h0 = fma-chain k=0..255 (single fp32 acc, ascending k),
//              h1 = fma-chain k=256..511, s = h0 + h1, v = clip(4*(s+x)).
//
// vs R9 (best): the SMEM reduce + per-step __syncthreads is replaced by a
// lane-pair shfl_xor(1) + FADD (commutative -> bit-exact in both lanes).
// Everything else identical: 4-CTA cluster, split barrier.cluster
// arrive/wait (measured best vs all mbarrier variants), W 3/4 in regs +
// 1/4 SMEM, overlap window (rp store + x prefetch) after arrive.
// ============================================================================
template <int NSTEPS>
__device__ __forceinline__ void rec_body(const float* __restrict__ x,
                                         const float* __restrict__ W) {
    extern __shared__ float sm[];
    float* feats = sm + FEAT_OFF;    // [2][520], halves at +0 / +260
    float* Wt    = sm + WT_OFF;      // [256][68], row = tid

    const int tid  = threadIdx.x;
    const int rank = blockIdx.x & 3;
    const int b    = blockIdx.x >> 2;
    const int col  = tid >> 1;        // 0..127
    const int h    = tid & 1;         // half (lane pair partner differs)
    const int j0   = rank * CPC;
    const int gj   = j0 + col;

    const uint32_t feats_u32 = smem_u32(feats);

    // SMEM quarter: own (col,h) groups g=4q+3 -> Wt[tid][q*4+j]  (one-time)
#pragma unroll
    for (int q = 0; q < 16; q++)
#pragma unroll
        for (int j = 0; j < 4; j++) {
            int k = h * 256 + 16 * q + 12 + j;
            Wt[tid * WT_STRIDE + q * 4 + j] = W[(size_t)k * DD + gj];
        }
    for (int e = tid; e < 2 * FBUF; e += TPC) feats[e] = 0.f;

    // Register-pinned 3/4: own half, groups g=4q+m (m=0..2)
    float wreg[192];
#pragma unroll
    for (int q = 0; q < 16; q++)
#pragma unroll
        for (int m = 0; m < 3; m++)
#pragma unroll
            for (int j = 0; j < 4; j++) {
                int k = h * 256 + 16 * q + 4 * m + j;
                wreg[(q * 3 + m) * 4 + j] = W[(size_t)k * DD + gj];
            }

    const float4* __restrict__ wq4 =
        (const float4*)(Wt + tid * WT_STRIDE);               // 16 groups
    const float* __restrict__ xp = x + ((size_t)b * DD + gj) * TT;
    float* __restrict__ rp = g_resbuf + ((size_t)b * DD + gj) * TT;

    // slot of this column's value within a feat buffer (halves padded apart)
    const uint32_t slot = (uint32_t)(gj + ((gj >= 256) ? 4 : 0));

    float xv_next = __ldg(xp);    // x for t=0 (both lanes load same addr)

    __syncthreads();
    cluster_sync_();              // feats zero + Wt visible cluster-wide

    for (int t = 0; t < NSTEPS; t++) {
        if (t) cluster_wait_();   // completes phase t-1
        const float xv = xv_next;

        // 256-long single-accumulator fma chain, ascending k (own half).
        const float4* __restrict__ f4 =
            (const float4*)(feats + (t & 1) * FBUF + h * 260);
        float a = 0.f;
#pragma unroll
        for (int q = 0; q < 16; q++) {
#pragma unroll
            for (int m = 0; m < 3; m++) {
                const float4 f = f4[4 * q + m];
                const int wb = (q * 3 + m) * 4;
                a = fmaf(f.x, wreg[wb + 0], a);
                a = fmaf(f.y, wreg[wb + 1], a);
                a = fmaf(f.z, wreg[wb + 2], a);
                a = fmaf(f.w, wreg[wb + 3], a);
            }
            const float4 f = f4[4 * q + 3];
            const float4 w = wq4[q];
            a = fmaf(f.x, w.x, a);
            a = fmaf(f.y, w.y, a);
            a = fmaf(f.z, w.z, a);
            a = fmaf(f.w, w.w, a);
        }

        // combine halves via lane-pair shuffle (commutative add -> both
        // lanes hold the bit-exact h0+h1)
        const float a_other = __shfl_xor_sync(0xffffffffu, a, 1);
        const float s = a + a_other;
        const float v = fminf(1.f, fmaxf(-1.f, 4.f * (s + xv)));

        if (t < NSTEPS - 1) {
            // each lane pushes to its half's two ranks (all 4 ranks covered)
            const uint32_t dst =
                feats_u32 + (((uint32_t)((t & 1) ^ 1)) * FBUF + slot) * 4u;
            st_cluster_f32(dst, (uint32_t)(2 * h), v);
            st_cluster_f32(dst, (uint32_t)(2 * h + 1), v);
            cluster_arrive_();
            // overlap window: non-critical work while peers arrive
            if (h == 0) rp[t] = v;
            xv_next = __ldg(xp + t + 1);
        } else {
            if (h == 0) rp[t] = v;
        }
    }
}

__global__ void __cluster_dims__(CLU, 1, 1) __launch_bounds__(TPC, 1)
rec_kernel(const float* __restrict__ x, const float* __restrict__ W) {
    rec_body<TT>(x, W);
}

// ============================================================================
// Projection: out[b][o][t] = sum_i lin_w[o][i] * resbuf[b][i][t] + lin_b[o]
// 128x128 tile, 8x8 microtile, packed fma.rn.f32x2 (FFMA2).
// ============================================================================
typedef unsigned long long u64;
#define FMA2(d, a, bv) \
    asm("fma.rn.f32x2 %0, %1, %2, %0;" : "+l"(d) : "l"(a), "l"(bv))
#define PACK2(o, lo, hi) \
    asm("mov.b64 %0, {%1, %2};" : "=l"(o) : "f"(lo), "f"(hi))
#define UNPACK2(lo, hi, v) \
    asm("mov.b64 {%0, %1}, %2;" : "=f"(lo), "=f"(hi) : "l"(v))

__global__ void __launch_bounds__(256) proj_kernel(
    const float* __restrict__ lin_w, const float* __restrict__ lin_b,
    float* __restrict__ out) {

    const float* rb = g_resbuf;
    const int b  = blockIdx.z;
    const int o0 = blockIdx.y * 128;
    const int t0 = blockIdx.x * 128;

    __shared__ float As[8][128];
    __shared__ float Bs[8][128];

    const int tid = threadIdx.x;
    const int tx  = tid & 15;
    const int ty  = tid >> 4;

    u64 acc2[8][4];
#pragma unroll
    for (int r = 0; r < 8; r++)
#pragma unroll
        for (int c = 0; c < 4; c++) acc2[r][c] = 0ull;

    const int lo   = tid >> 1;
    const int half = (tid & 1) * 4;
    const int brow = tid >> 5;
    const int bc4  = (tid & 31) * 4;

    for (int k0 = 0; k0 < DD; k0 += 8) {
        float4 av = *(const float4*)&lin_w[(size_t)(o0 + lo) * DD + k0 + half];
        float4 bv = *(const float4*)&rb[((size_t)b * DD + k0 + brow) * TT + t0 + bc4];
        __syncthreads();
        As[half + 0][lo] = av.x; As[half + 1][lo] = av.y;
        As[half + 2][lo] = av.z; As[half + 3][lo] = av.w;
        *(float4*)&Bs[brow][bc4] = bv;
        __syncthreads();

#pragma unroll
        for (int ii = 0; ii < 8; ii++) {
            float4 a0 = *(const float4*)&As[ii][ty * 4];
            float4 a1 = *(const float4*)&As[ii][64 + ty * 4];
            float4 b0 = *(const float4*)&Bs[ii][tx * 4];
            float4 b1 = *(const float4*)&Bs[ii][64 + tx * 4];
            u64 b2[4];
            PACK2(b2[0], b0.x, b0.y); PACK2(b2[1], b0.z, b0.w);
            PACK2(b2[2], b1.x, b1.y); PACK2(b2[3], b1.z, b1.w);
            float a[8] = {a0.x, a0.y, a0.z, a0.w, a1.x, a1.y, a1.z, a1.w};
#pragma unroll
            for (int r = 0; r < 8; r++) {
                u64 a2;
                PACK2(a2, a[r], a[r]);
                FMA2(acc2[r][0], a2, b2[0]);
                FMA2(acc2[r][1], a2, b2[1]);
                FMA2(acc2[r][2], a2, b2[2]);
                FMA2(acc2[r][3], a2, b2[3]);
            }
        }
    }

#pragma unroll
    for (int g = 0; g < 2; g++) {
#pragma unroll
        for (int r = 0; r < 4; r++) {
            const int ar = g * 4 + r;
            const int o  = o0 + g * 64 + ty * 4 + r;
            const float bias = lin_b[o];
            float c0, c1, c2, c3, c4, c5, c6, c7;
            UNPACK2(c0, c1, acc2[ar][0]); UNPACK2(c2, c3, acc2[ar][1]);
            UNPACK2(c4, c5, acc2[ar][2]); UNPACK2(c6, c7, acc2[ar][3]);
            float4 v0, v1;
            v0.x = c0 + bias; v0.y = c1 + bias; v0.z = c2 + bias; v0.w = c3 + bias;
            v1.x = c4 + bias; v1.y = c5 + bias; v1.z = c6 + bias; v1.w = c7 + bias;
            float* op = &out[((size_t)b * DD + o) * TT + t0];
            *(float4*)(op + tx * 4)      = v0;
            *(float4*)(op + 64 + tx * 4) = v1;
        }
    }
}

extern "C" void kernel_launch(void* const* d_in, const int* in_sizes, int n_in,
                              void* d_out, int out_size) {
    const float* x     = (const float*)d_in[0];
    const float* W     = (const float*)d_in[1];
    const float* lin_w = (const float*)d_in[2];
    const float* lin_b = (const float*)d_in[3];
    float* out = (float*)d_out;

    cudaFuncSetAttribute(rec_kernel,
                         cudaFuncAttributeMaxDynamicSharedMemorySize,
                         SMEM_REC_BYTES);
    rec_kernel<<<dim3(BB * CLU), TPC, SMEM_REC_BYTES>>>(x, W);
    proj_kernel<<<dim3(TT / 128, DD / 128, BB), 256>>>(lin_w, lin_b, out);
}

// round 13
// speedup vs baseline: 1.0954x; 1.0284x over previous
#include <cuda_runtime.h>
#include <cstdint>

#define BB 16
#define DD 512
#define TT 4096

// recurrence: 16 clusters (=batches) x 4 CTAs (=128-col slices) x 256 threads
// warps 0-3 = h0 (cols 0..127), warps 4-7 = h1 (same cols)
#define CLU 4
#define TPC 256
#define CPC 128
// smem layout (float offsets)
#define REDA_OFF 0
#define REDB_OFF 128
#define FEAT_OFF 256                       // [2][512]
#define WT_OFF   (FEAT_OFF + 2 * DD)       // 1280
#define WT_STRIDE 36                       // 9 float4; ≡4 (mod 32) -> optimal 4-wf LDS.128
#define SMEM_REC_FLOATS (WT_OFF + 256 * WT_STRIDE)   // 10496
#define SMEM_REC_BYTES (SMEM_REC_FLOATS * 4)         // 41984

// resbuf[b][i][t]  (128 MB) static scratch
__device__ float g_resbuf[(size_t)BB * DD * TT];

__device__ __forceinline__ uint32_t smem_u32(const void* p) {
    uint32_t a;
    asm("{ .reg .u64 t; cvta.to.shared.u64 t, %1; cvt.u32.u64 %0, t; }" : "=r"(a) : "l"(p));
    return a;
}
__device__ __forceinline__ void st_cluster_f32(uint32_t addr, uint32_t rank, float v) {
    asm volatile("{ .reg .u32 r; mapa.shared::cluster.u32 r, %0, %1; st.shared::cluster.f32 [r], %2; }"
                 :: "r"(addr), "r"(rank), "f"(v) : "memory");
}
__device__ __forceinline__ void cluster_arrive_() {
    asm volatile("barrier.cluster.arrive.aligned;" ::: "memory");
}
__device__ __forceinline__ void cluster_wait_() {
    asm volatile("barrier.cluster.wait.aligned;" ::: "memory");
}
__device__ __forceinline__ void cluster_sync_() {
    cluster_arrive_(); cluster_wait_();
}
__device__ __forceinline__ void pair_bar(int id) {
    asm volatile("bar.sync %0, 64;" :: "r"(id) : "memory");
}

// ============================================================================
// Recurrence, ordering "C" (bit-exact, verified rounds 5-12):
// per element: h0 = fma-chain k=0..255 (single fp32 acc, ascending k),
//              h1 = fma-chain k=256..511, s = h0 + h1, v = clip(4*(s+x)).
//
// vs R9 (best): W pinned 7/8 in registers (224/thread; only every 8th
// 4-k-group from SMEM) -> per-SM LDS wavefronts 1024 -> ~768 < 1024-cyc
// chain, crossbar off the critical path. Per-pair named barriers (warp w
// with w+4, 64 threads) replace the 256-thread __syncthreads for the
// half-combine. Epilogue duties split: h0 pushes ranks 0-1, h1 stores rp.
// Sync primitive: split barrier.cluster arrive/wait (measured best).
// ============================================================================
template <int NSTEPS>
__device__ __forceinline__ void rec_body(const float* __restrict__ x,
                                         const float* __restrict__ W) {
    extern __shared__ float sm[];
    float* redA  = sm + REDA_OFF;    // [128] h0 partials
    float* redB  = sm + REDB_OFF;    // [128] h1 partials
    float* feats = sm + FEAT_OFF;    // [2][512]
    float* Wt    = sm + WT_OFF;      // [256][36], row = tid

    const int tid  = threadIdx.x;
    const int rank = blockIdx.x & 3;
    const int b    = blockIdx.x >> 2;
    const int col  = tid & 127;
    const int h    = tid >> 7;        // 0 or 1 (which 256-half)
    const int pid  = ((tid >> 5) & 3) + 1;   // named-barrier id (1..4)
    const int j0   = rank * CPC;
    const int gj   = j0 + col;

    const uint32_t feats_u32 = smem_u32(feats);

    // SMEM eighth: own (col,h) groups g with g%8==7 -> Wt[tid][q8*4+j]
#pragma unroll
    for (int q8 = 0; q8 < 8; q8++)
#pragma unroll
        for (int j = 0; j < 4; j++) {
            int k = h * 256 + 32 * q8 + 28 + j;
            Wt[tid * WT_STRIDE + q8 * 4 + j] = W[(size_t)k * DD + gj];
        }
    for (int e = tid; e < 2 * DD; e += TPC) feats[e] = 0.f;

    // Register-pinned 7/8: own half, groups g = 8*q8 + m (m = 0..6)
    float wreg[224];
#pragma unroll
    for (int q8 = 0; q8 < 8; q8++)
#pragma unroll
        for (int m = 0; m < 7; m++)
#pragma unroll
            for (int j = 0; j < 4; j++) {
                int k = h * 256 + 32 * q8 + 4 * m + j;
                wreg[(q8 * 7 + m) * 4 + j] = W[(size_t)k * DD + gj];
            }

    const float4* __restrict__ wq4 =
        (const float4*)(Wt + tid * WT_STRIDE);               // 8 groups
    const float* __restrict__ xp = x + ((size_t)b * DD + gj) * TT;
    float* __restrict__ rp = g_resbuf + ((size_t)b * DD + gj) * TT;

    float xv_next = __ldg(xp);    // x for t=0

    __syncthreads();
    cluster_sync_();              // feats zero + Wt visible cluster-wide

    for (int t = 0; t < NSTEPS; t++) {
        if (t) cluster_wait_();   // completes phase t-1
        const float xv = xv_next;

        // 256-long single-accumulator fma chain, ascending k (own half).
        // groups 8q8+{0..6} from regs, 8q8+7 from SMEM; order == ascending k.
        const float4* __restrict__ f4 =
            (const float4*)(feats + (t & 1) * DD) + h * 64;
        float a = 0.f;
#pragma unroll
        for (int q8 = 0; q8 < 8; q8++) {
#pragma unroll
            for (int m = 0; m < 7; m++) {
                const float4 f = f4[8 * q8 + m];
                const int wb = (q8 * 7 + m) * 4;
                a = fmaf(f.x, wreg[wb + 0], a);
                a = fmaf(f.y, wreg[wb + 1], a);
                a = fmaf(f.z, wreg[wb + 2], a);
                a = fmaf(f.w, wreg[wb + 3], a);
            }
            const float4 f = f4[8 * q8 + 7];
            const float4 w = wq4[q8];
            a = fmaf(f.x, w.x, a);
            a = fmaf(f.y, w.y, a);
            a = fmaf(f.z, w.z, a);
            a = fmaf(f.w, w.w, a);
        }

        // half-combine via per-pair named barrier (warp w <-> warp w+4)
        if (h == 0) redA[col] = a; else redB[col] = a;
        pair_bar(pid);
        const float s = redA[col] + redB[col];       // h0 + h1 (exact order)
        const float v = fminf(1.f, fmaxf(-1.f, 4.f * (s + xv)));

        if (t < NSTEPS - 1) {
            const uint32_t dst =
                feats_u32 + (uint32_t)((((t & 1) ^ 1)) * DD + gj) * 4u;
            // h0 pushes ranks 0-1; h1 pushes ranks 2-3 (all ranks covered)
            st_cluster_f32(dst, (uint32_t)(2 * h), v);
            st_cluster_f32(dst, (uint32_t)(2 * h + 1), v);
            cluster_arrive_();
            // overlap window: non-critical work while peers arrive
            if (h == 1) rp[t] = v;
            xv_next = __ldg(xp + t + 1);
        } else {
            if (h == 1) rp[t] = v;
        }
    }
}

__global__ void __cluster_dims__(CLU, 1, 1) __launch_bounds__(TPC, 1)
rec_kernel(const float* __restrict__ x, const float* __restrict__ W) {
    rec_body<TT>(x, W);
}

// ============================================================================
// Projection: out[b][o][t] = sum_i lin_w[o][i] * resbuf[b][i][t] + lin_b[o]
// 128x128 tile, 8x8 microtile, packed fma.rn.f32x2 (FFMA2).
// ============================================================================
typedef unsigned long long u64;
#define FMA2(d, a, bv) \
    asm("fma.rn.f32x2 %0, %1, %2, %0;" : "+l"(d) : "l"(a), "l"(bv))
#define PACK2(o, lo, hi) \
    asm("mov.b64 %0, {%1, %2};" : "=l"(o) : "f"(lo), "f"(hi))
#define UNPACK2(lo, hi, v) \
    asm("mov.b64 {%0, %1}, %2;" : "=f"(lo), "=f"(hi) : "l"(v))

__global__ void __launch_bounds__(256) proj_kernel(
    const float* __restrict__ lin_w, const float* __restrict__ lin_b,
    float* __restrict__ out) {

    const float* rb = g_resbuf;
    const int b  = blockIdx.z;
    const int o0 = blockIdx.y * 128;
    const int t0 = blockIdx.x * 128;

    __shared__ float As[8][128];
    __shared__ float Bs[8][128];

    const int tid = threadIdx.x;
    const int tx  = tid & 15;
    const int ty  = tid >> 4;

    u64 acc2[8][4];
#pragma unroll
    for (int r = 0; r < 8; r++)
#pragma unroll
        for (int c = 0; c < 4; c++) acc2[r][c] = 0ull;

    const int lo   = tid >> 1;
    const int half = (tid & 1) * 4;
    const int brow = tid >> 5;
    const int bc4  = (tid & 31) * 4;

    for (int k0 = 0; k0 < DD; k0 += 8) {
        float4 av = *(const float4*)&lin_w[(size_t)(o0 + lo) * DD + k0 + half];
        float4 bv = *(const float4*)&rb[((size_t)b * DD + k0 + brow) * TT + t0 + bc4];
        __syncthreads();
        As[half + 0][lo] = av.x; As[half + 1][lo] = av.y;
        As[half + 2][lo] = av.z; As[half + 3][lo] = av.w;
        *(float4*)&Bs[brow][bc4] = bv;
        __syncthreads();

#pragma unroll
        for (int ii = 0; ii < 8; ii++) {
            float4 a0 = *(const float4*)&As[ii][ty * 4];
            float4 a1 = *(const float4*)&As[ii][64 + ty * 4];
            float4 b0 = *(const float4*)&Bs[ii][tx * 4];
            float4 b1 = *(const float4*)&Bs[ii][64 + tx * 4];
            u64 b2[4];
            PACK2(b2[0], b0.x, b0.y); PACK2(b2[1], b0.z, b0.w);
            PACK2(b2[2], b1.x, b1.y); PACK2(b2[3], b1.z, b1.w);
            float a[8] = {a0.x, a0.y, a0.z, a0.w, a1.x, a1.y, a1.z, a1.w};
#pragma unroll
            for (int r = 0; r < 8; r++) {
                u64 a2;
                PACK2(a2, a[r], a[r]);
                FMA2(acc2[r][0], a2, b2[0]);
                FMA2(acc2[r][1], a2, b2[1]);
                FMA2(acc2[r][2], a2, b2[2]);
                FMA2(acc2[r][3], a2, b2[3]);
            }
        }
    }

#pragma unroll
    for (int g = 0; g < 2; g++) {
#pragma unroll
        for (int r = 0; r < 4; r++) {
            const int ar = g * 4 + r;
            const int o  = o0 + g * 64 + ty * 4 + r;
            const float bias = lin_b[o];
            float c0, c1, c2, c3, c4, c5, c6, c7;
            UNPACK2(c0, c1, acc2[ar][0]); UNPACK2(c2, c3, acc2[ar][1]);
            UNPACK2(c4, c5, acc2[ar][2]); UNPACK2(c6, c7, acc2[ar][3]);
            float4 v0, v1;
            v0.x = c0 + bias; v0.y = c1 + bias; v0.z = c2 + bias; v0.w = c3 + bias;
            v1.x = c4 + bias; v1.y = c5 + bias; v1.z = c6 + bias; v1.w = c7 + bias;
            float* op = &out[((size_t)b * DD + o) * TT + t0];
            *(float4*)(op + tx * 4)      = v0;
            *(float4*)(op + 64 + tx * 4) = v1;
        }
    }
}

extern "C" void kernel_launch(void* const* d_in, const int* in_sizes, int n_in,
                              void* d_out, int out_size) {
    const float* x     = (const float*)d_in[0];
    const float* W     = (const float*)d_in[1];
    const float* lin_w = (const float*)d_in[2];
    const float* lin_b = (const float*)d_in[3];
    float* out = (float*)d_out;

    cudaFuncSetAttribute(rec_kernel,
                         cudaFuncAttributeMaxDynamicSharedMemorySize,
                         SMEM_REC_BYTES);
    rec_kernel<<<dim3(BB * CLU), TPC, SMEM_REC_BYTES>>>(x, W);
    proj_kernel<<<dim3(TT / 128, DD / 128, BB), 256>>>(lin_w, lin_b, out);
}

// round 14
// speedup vs baseline: 1.1773x; 1.0747x over previous
#include <cuda_runtime.h>
#include <cstdint>

#define BB 16
#define DD 512
#define TT 4096

// recurrence: 16 clusters (=batches) x 4 CTAs (=128-col slices) x 256 threads
#define CLU 4
#define TPC 256
#define CPC 128
// smem layout (float offsets)
#define REDA_OFF 0
#define REDB_OFF 128
#define FEAT_OFF 256                       // [2][512]
#define WT_OFF   (FEAT_OFF + 2 * DD)       // 1280
#define WT_STRIDE 68                       // 17 float4: conflict-free LDS.128
#define SMEM_REC_FLOATS (WT_OFF + 256 * WT_STRIDE)   // 18688
#define SMEM_REC_BYTES (SMEM_REC_FLOATS * 4)         // 74752

// resbuf[b][i][t]  (128 MB) static scratch
__device__ float g_resbuf[(size_t)BB * DD * TT];

__device__ __forceinline__ uint32_t smem_u32(const void* p) {
    uint32_t a;
    asm("{ .reg .u64 t; cvta.to.shared.u64 t, %1; cvt.u32.u64 %0, t; }" : "=r"(a) : "l"(p));
    return a;
}
// address translation hoisted: map a local smem address into peer rank's CTA
__device__ __forceinline__ uint32_t mapa_cluster(uint32_t addr, uint32_t rank) {
    uint32_t r;
    asm("mapa.shared::cluster.u32 %0, %1, %2;" : "=r"(r) : "r"(addr), "r"(rank));
    return r;
}
__device__ __forceinline__ void st_cluster_pre(uint32_t mapped_addr, float v) {
    asm volatile("st.shared::cluster.f32 [%0], %1;"
                 :: "r"(mapped_addr), "f"(v) : "memory");
}
__device__ __forceinline__ void cluster_arrive_() {
    asm volatile("barrier.cluster.arrive.aligned;" ::: "memory");
}
__device__ __forceinline__ void cluster_wait_() {
    asm volatile("barrier.cluster.wait.aligned;" ::: "memory");
}
__device__ __forceinline__ void cluster_sync_() {
    cluster_arrive_(); cluster_wait_();
}

// ============================================================================
// Recurrence, ordering "C" (bit-exact, verified rounds 5-13):
// per element: h0 = fma-chain k=0..255 (single fp32 acc, ascending k),
//              h1 = fma-chain k=256..511, s = h0 + h1, v = clip(4*(s+x)).
//
// Config = R9, the measured optimum (1.49us/step): 4-CTA cluster, 256
// threads (2 warps/SMSP: FMA issue 1024 cyc == 1024-cyc chain latency,
// crossbar ~1024 wf -- exactly balanced), W 3/4 in regs + 1/4 SMEM,
// SMEM reduce + __syncthreads for the half-combine, split barrier.cluster
// arrive/wait with rp-store + x-prefetch in the overlap window.
// New vs R9: broadcast destinations fully precomputed (mapa hoisted out of
// the loop -- push is two bare st.shared::cluster).
// ============================================================================
__global__ void __cluster_dims__(CLU, 1, 1) __launch_bounds__(TPC, 1)
rec_kernel(const float* __restrict__ x, const float* __restrict__ W) {
    extern __shared__ float sm[];
    float* redA  = sm + REDA_OFF;    // [128] h0 partials
    float* redB  = sm + REDB_OFF;    // [128] h1 partials
    float* feats = sm + FEAT_OFF;    // [2][512]
    float* Wt    = sm + WT_OFF;      // [256][68]

    const int tid  = threadIdx.x;
    const int rank = blockIdx.x & 3;
    const int b    = blockIdx.x >> 2;
    const int col  = tid & 127;
    const int h    = tid >> 7;        // 0 or 1 (which 256-half)
    const int j0   = rank * CPC;
    const int gj   = j0 + col;

    // SMEM quarter (groups g=4q+3 of both halves), coalesced over columns
    for (int e = tid; e < 256 * 64; e += TPC) {
        int colr = e & 127;
        int j    = (e >> 7) & 3;
        int q    = (e >> 9) & 15;
        int hr   = e >> 13;
        int k    = hr * 256 + 16 * q + 12 + j;
        Wt[(hr * 128 + colr) * WT_STRIDE + q * 4 + j] =
            W[(size_t)k * DD + j0 + colr];
    }
    for (int e = tid; e < 2 * DD; e += TPC) feats[e] = 0.f;

    // Register-pinned 3/4: own half, groups g=4q+m (m=0..2)
    float wreg[192];
#pragma unroll
    for (int q = 0; q < 16; q++)
#pragma unroll
        for (int m = 0; m < 3; m++)
#pragma unroll
            for (int j = 0; j < 4; j++) {
                int k = h * 256 + 16 * q + 4 * m + j;
                wreg[(q * 3 + m) * 4 + j] = W[(size_t)k * DD + gj];
            }

    const float4* __restrict__ wq4 =
        (const float4*)(Wt + (h * 128 + col) * WT_STRIDE);   // 16 groups
    const float* __restrict__ xp = x + ((size_t)b * DD + gj) * TT;
    float* __restrict__ rp = g_resbuf + ((size_t)b * DD + gj) * TT;

    // Precomputed broadcast destinations: this thread pushes column gj into
    // ranks {2h, 2h+1}, for each feat-buffer parity. Fully loop-invariant.
    const uint32_t feats_u32 = smem_u32(feats);
    const uint32_t dst_b0 = feats_u32 + (uint32_t)gj * 4u;          // buffer 0
    const uint32_t dst_b1 = dst_b0 + (uint32_t)DD * 4u;             // buffer 1
    const uint32_t ra = (uint32_t)(2 * h), rb_ = ra + 1u;
    const uint32_t d0a = mapa_cluster(dst_b0, ra);
    const uint32_t d0b = mapa_cluster(dst_b0, rb_);
    const uint32_t d1a = mapa_cluster(dst_b1, ra);
    const uint32_t d1b = mapa_cluster(dst_b1, rb_);

    float xv_next = __ldg(xp);    // x for t=0

    __syncthreads();
    cluster_sync_();              // feats zero + Wt visible cluster-wide

    for (int t = 0; t < TT; t++) {
        if (t) cluster_wait_();   // completes phase t-1
        const float xv = xv_next;

        // 256-long single-accumulator fma chain, ascending k (own half).
        const float4* __restrict__ f4 =
            (const float4*)(feats + (t & 1) * DD) + h * 64;
        float a = 0.f;
#pragma unroll
        for (int q = 0; q < 16; q++) {
#pragma unroll
            for (int m = 0; m < 3; m++) {
                const float4 f = f4[4 * q + m];
                const int wb = (q * 3 + m) * 4;
                a = fmaf(f.x, wreg[wb + 0], a);
                a = fmaf(f.y, wreg[wb + 1], a);
                a = fmaf(f.z, wreg[wb + 2], a);
                a = fmaf(f.w, wreg[wb + 3], a);
            }
            const float4 f = f4[4 * q + 3];
            const float4 w = wq4[q];
            a = fmaf(f.x, w.x, a);
            a = fmaf(f.y, w.y, a);
            a = fmaf(f.z, w.z, a);
            a = fmaf(f.w, w.w, a);
        }

        if (h == 0) redA[col] = a; else redB[col] = a;
        __syncthreads();

        const float s = redA[col] + redB[col];       // h0 + h1 (exact order)
        const float v = fminf(1.f, fmaxf(-1.f, 4.f * (s + xv)));

        if (t < TT - 1) {
            // push into next-parity buffer of this half's two ranks
            if ((t & 1) == 0) {       // next buffer = 1
                st_cluster_pre(d1a, v);
                st_cluster_pre(d1b, v);
            } else {                  // next buffer = 0
                st_cluster_pre(d0a, v);
                st_cluster_pre(d0b, v);
            }
            cluster_arrive_();
            // overlap window: non-critical work while peers arrive
            if (h == 0) rp[t] = v;
            xv_next = __ldg(xp + t + 1);
        } else {
            if (h == 0) rp[t] = v;
        }
    }
}

// ============================================================================
// Projection: out[b][o][t] = sum_i lin_w[o][i] * resbuf[b][i][t] + lin_b[o]
// 128x128 tile, 8x8 microtile, packed fma.rn.f32x2 (FFMA2), conflict-free
// {q, 64+q} float4 phases. Measured 655us.
// ============================================================================
typedef unsigned long long u64;
#define FMA2(d, a, bv) \
    asm("fma.rn.f32x2 %0, %1, %2, %0;" : "+l"(d) : "l"(a), "l"(bv))
#define PACK2(o, lo, hi) \
    asm("mov.b64 %0, {%1, %2};" : "=l"(o) : "f"(lo), "f"(hi))
#define UNPACK2(lo, hi, v) \
    asm("mov.b64 {%0, %1}, %2;" : "=f"(lo), "=f"(hi) : "l"(v))

__global__ void __launch_bounds__(256) proj_kernel(
    const float* __restrict__ lin_w, const float* __restrict__ lin_b,
    float* __restrict__ out) {

    const float* rb = g_resbuf;
    const int b  = blockIdx.z;
    const int o0 = blockIdx.y * 128;
    const int t0 = blockIdx.x * 128;

    __shared__ float As[8][128];
    __shared__ float Bs[8][128];

    const int tid = threadIdx.x;
    const int tx  = tid & 15;
    const int ty  = tid >> 4;

    u64 acc2[8][4];
#pragma unroll
    for (int r = 0; r < 8; r++)
#pragma unroll
        for (int c = 0; c < 4; c++) acc2[r][c] = 0ull;

    const int lo   = tid >> 1;
    const int half = (tid & 1) * 4;
    const int brow = tid >> 5;
    const int bc4  = (tid & 31) * 4;

    for (int k0 = 0; k0 < DD; k0 += 8) {
        float4 av = *(const float4*)&lin_w[(size_t)(o0 + lo) * DD + k0 + half];
        float4 bv = *(const float4*)&rb[((size_t)b * DD + k0 + brow) * TT + t0 + bc4];
        __syncthreads();
        As[half + 0][lo] = av.x; As[half + 1][lo] = av.y;
        As[half + 2][lo] = av.z; As[half + 3][lo] = av.w;
        *(float4*)&Bs[brow][bc4] = bv;
        __syncthreads();

#pragma unroll
        for (int ii = 0; ii < 8; ii++) {
            float4 a0 = *(const float4*)&As[ii][ty * 4];
            float4 a1 = *(const float4*)&As[ii][64 + ty * 4];
            float4 b0 = *(const float4*)&Bs[ii][tx * 4];
            float4 b1 = *(const float4*)&Bs[ii][64 + tx * 4];
            u64 b2[4];
            PACK2(b2[0], b0.x, b0.y); PACK2(b2[1], b0.z, b0.w);
            PACK2(b2[2], b1.x, b1.y); PACK2(b2[3], b1.z, b1.w);
            float a[8] = {a0.x, a0.y, a0.z, a0.w, a1.x, a1.y, a1.z, a1.w};
#pragma unroll
            for (int r = 0; r < 8; r++) {
                u64 a2;
                PACK2(a2, a[r], a[r]);
                FMA2(acc2[r][0], a2, b2[0]);
                FMA2(acc2[r][1], a2, b2[1]);
                FMA2(acc2[r][2], a2, b2[2]);
                FMA2(acc2[r][3], a2, b2[3]);
            }
        }
    }

#pragma unroll
    for (int g = 0; g < 2; g++) {
#pragma unroll
        for (int r = 0; r < 4; r++) {
            const int ar = g * 4 + r;
            const int o  = o0 + g * 64 + ty * 4 + r;
            const float bias = lin_b[o];
            float c0, c1, c2, c3, c4, c5, c6, c7;
            UNPACK2(c0, c1, acc2[ar][0]); UNPACK2(c2, c3, acc2[ar][1]);
            UNPACK2(c4, c5, acc2[ar][2]); UNPACK2(c6, c7, acc2[ar][3]);
            float4 v0, v1;
            v0.x = c0 + bias; v0.y = c1 + bias; v0.z = c2 + bias; v0.w = c3 + bias;
            v1.x = c4 + bias; v1.y = c5 + bias; v1.z = c6 + bias; v1.w = c7 + bias;
            float* op = &out[((size_t)b * DD + o) * TT + t0];
            *(float4*)(op + tx * 4)      = v0;
            *(float4*)(op + 64 + tx * 4) = v1;
        }
    }
}

extern "C" void kernel_launch(void* const* d_in, const int* in_sizes, int n_in,
                              void* d_out, int out_size) {
    const float* x     = (const float*)d_in[0];
    const float* W     = (const float*)d_in[1];
    const float* lin_w = (const float*)d_in[2];
    const float* lin_b = (const float*)d_in[3];
    float* out = (float*)d_out;

    cudaFuncSetAttribute(rec_kernel,
                         cudaFuncAttributeMaxDynamicSharedMemorySize,
                         SMEM_REC_BYTES);
    rec_kernel<<<dim3(BB * CLU), TPC, SMEM_REC_BYTES>>>(x, W);
    proj_kernel<<<dim3(TT / 128, DD / 128, BB), 256>>>(lin_w, lin_b, out);
}

// round 15
// speedup vs baseline: 1.2711x; 1.0797x over previous
#include <cuda_runtime.h>
#include <cstdint>

#define BB 16
#define DD 512
#define TT 4096

// merged grid: 36 clusters x 4 CTAs = 144 CTAs, 256 threads each.
// blocks 0..63  : recurrence (16 clusters = batches), then join proj queue
// blocks 64..143: projection workers from t=0
#define CLU 4
#define TPC 256
#define CPC 128
#define NREC 64
#define NGRID 144
#define NTILES 2048          // 32 t-slices x 16 batches x 4 o-blocks

// rec smem layout (float offsets)
#define REDA_OFF 0
#define REDB_OFF 128
#define FEAT_OFF 256                       // [2][512]
#define WT_OFF   (FEAT_OFF + 2 * DD)       // 1280
#define WT_STRIDE 68
#define SMEM_REC_FLOATS (WT_OFF + 256 * WT_STRIDE)   // 18688
#define SMEM_REC_BYTES (SMEM_REC_FLOATS * 4)         // 74752

// resbuf[b][i][t]  (128 MB) static scratch
__device__ float    g_resbuf[(size_t)BB * DD * TT];
__device__ int      g_prog[BB * CLU];     // steps completed per (batch, rank)
__device__ unsigned g_ticket;             // proj tile ticket

__global__ void init_kernel() {
    int i = threadIdx.x;
    if (i < BB * CLU) g_prog[i] = 0;
    if (i == 0) g_ticket = 0u;
}

__device__ __forceinline__ uint32_t smem_u32(const void* p) {
    uint32_t a;
    asm("{ .reg .u64 t; cvta.to.shared.u64 t, %1; cvt.u32.u64 %0, t; }" : "=r"(a) : "l"(p));
    return a;
}
__device__ __forceinline__ uint32_t mapa_cluster(uint32_t addr, uint32_t rank) {
    uint32_t r;
    asm("mapa.shared::cluster.u32 %0, %1, %2;" : "=r"(r) : "r"(addr), "r"(rank));
    return r;
}
__device__ __forceinline__ void st_cluster_pre(uint32_t mapped_addr, float v) {
    asm volatile("st.shared::cluster.f32 [%0], %1;"
                 :: "r"(mapped_addr), "f"(v) : "memory");
}
__device__ __forceinline__ void cluster_arrive_() {
    asm volatile("barrier.cluster.arrive.aligned;" ::: "memory");
}
__device__ __forceinline__ void cluster_wait_() {
    asm volatile("barrier.cluster.wait.aligned;" ::: "memory");
}
__device__ __forceinline__ void cluster_sync_() {
    cluster_arrive_(); cluster_wait_();
}
__device__ __forceinline__ int ld_acq(const int* p) {
    int v;
    asm volatile("ld.acquire.gpu.global.s32 %0, [%1];" : "=r"(v) : "l"(p) : "memory");
    return v;
}

typedef unsigned long long u64;
#define FMA2(d, a, bv) \
    asm("fma.rn.f32x2 %0, %1, %2, %0;" : "+l"(d) : "l"(a), "l"(bv))
#define PACK2(o, lo, hi) \
    asm("mov.b64 %0, {%1, %2};" : "=l"(o) : "f"(lo), "f"(hi))
#define UNPACK2(lo, hi, v) \
    asm("mov.b64 {%0, %1}, %2;" : "=f"(lo), "=f"(hi) : "l"(v))

// ============================================================================
// Projection tile: out[b][o0..o0+128)[t0..t0+128) via FFMA2, identical math
// (and therefore bit-identical output) to the standalone R14 proj kernel.
// ============================================================================
__device__ void proj_tile(float* sm, int b, int o0, int t0,
                          const float* __restrict__ lin_w,
                          const float* __restrict__ lin_b,
                          float* __restrict__ out) {
    float* As = sm;           // [8][128]
    float* Bs = sm + 1024;    // [8][128]
    const float* rb = g_resbuf;

    const int tid = threadIdx.x;
    const int tx  = tid & 15;
    const int ty  = tid >> 4;

    u64 acc2[8][4];
#pragma unroll
    for (int r = 0; r < 8; r++)
#pragma unroll
        for (int c = 0; c < 4; c++) acc2[r][c] = 0ull;

    const int lo   = tid >> 1;
    const int half = (tid & 1) * 4;
    const int brow = tid >> 5;
    const int bc4  = (tid & 31) * 4;

    for (int k0 = 0; k0 < DD; k0 += 8) {
        float4 av = *(const float4*)&lin_w[(size_t)(o0 + lo) * DD + k0 + half];
        float4 bv = *(const float4*)&rb[((size_t)b * DD + k0 + brow) * TT + t0 + bc4];
        __syncthreads();
        As[(half + 0) * 128 + lo] = av.x; As[(half + 1) * 128 + lo] = av.y;
        As[(half + 2) * 128 + lo] = av.z; As[(half + 3) * 128 + lo] = av.w;
        *(float4*)&Bs[brow * 128 + bc4] = bv;
        __syncthreads();

#pragma unroll
        for (int ii = 0; ii < 8; ii++) {
            float4 a0 = *(const float4*)&As[ii * 128 + ty * 4];
            float4 a1 = *(const float4*)&As[ii * 128 + 64 + ty * 4];
            float4 b0 = *(const float4*)&Bs[ii * 128 + tx * 4];
            float4 b1 = *(const float4*)&Bs[ii * 128 + 64 + tx * 4];
            u64 b2[4];
            PACK2(b2[0], b0.x, b0.y); PACK2(b2[1], b0.z, b0.w);
            PACK2(b2[2], b1.x, b1.y); PACK2(b2[3], b1.z, b1.w);
            float a[8] = {a0.x, a0.y, a0.z, a0.w, a1.x, a1.y, a1.z, a1.w};
#pragma unroll
            for (int r = 0; r < 8; r++) {
                u64 a2;
                PACK2(a2, a[r], a[r]);
                FMA2(acc2[r][0], a2, b2[0]);
                FMA2(acc2[r][1], a2, b2[1]);
                FMA2(acc2[r][2], a2, b2[2]);
                FMA2(acc2[r][3], a2, b2[3]);
            }
        }
    }

#pragma unroll
    for (int g = 0; g < 2; g++) {
#pragma unroll
        for (int r = 0; r < 4; r++) {
            const int ar = g * 4 + r;
            const int o  = o0 + g * 64 + ty * 4 + r;
            const float bias = lin_b[o];
            float c0, c1, c2, c3, c4, c5, c6, c7;
            UNPACK2(c0, c1, acc2[ar][0]); UNPACK2(c2, c3, acc2[ar][1]);
            UNPACK2(c4, c5, acc2[ar][2]); UNPACK2(c6, c7, acc2[ar][3]);
            float4 v0, v1;
            v0.x = c0 + bias; v0.y = c1 + bias; v0.z = c2 + bias; v0.w = c3 + bias;
            v1.x = c4 + bias; v1.y = c5 + bias; v1.z = c6 + bias; v1.w = c7 + bias;
            float* op = &out[((size_t)b * DD + o) * TT + t0];
            *(float4*)(op + tx * 4)      = v0;
            *(float4*)(op + 64 + tx * 4) = v1;
        }
    }
}

// ============================================================================
// Merged kernel. Rec part = R14 exactly (ordering "C", bit-exact, 1.48us/step)
// plus progress publishing every 128 steps. All CTAs end in the proj queue.
// ============================================================================
__global__ void __cluster_dims__(CLU, 1, 1) __launch_bounds__(TPC, 1)
fused_kernel(const float* __restrict__ x, const float* __restrict__ W,
             const float* __restrict__ lin_w, const float* __restrict__ lin_b,
             float* __restrict__ out) {
    extern __shared__ float sm[];
    const int tid = threadIdx.x;
    const int bid = blockIdx.x;

    if (bid < NREC) {
        // ---------------- recurrence ----------------
        float* redA  = sm + REDA_OFF;
        float* redB  = sm + REDB_OFF;
        float* feats = sm + FEAT_OFF;
        float* Wt    = sm + WT_OFF;

        const int rank = bid & 3;
        const int b    = bid >> 2;
        const int col  = tid & 127;
        const int h    = tid >> 7;
        const int j0   = rank * CPC;
        const int gj   = j0 + col;

        for (int e = tid; e < 256 * 64; e += TPC) {
            int colr = e & 127;
            int j    = (e >> 7) & 3;
            int q    = (e >> 9) & 15;
            int hr   = e >> 13;
            int k    = hr * 256 + 16 * q + 12 + j;
            Wt[(hr * 128 + colr) * WT_STRIDE + q * 4 + j] =
                W[(size_t)k * DD + j0 + colr];
        }
        for (int e = tid; e < 2 * DD; e += TPC) feats[e] = 0.f;

        float wreg[192];
#pragma unroll
        for (int q = 0; q < 16; q++)
#pragma unroll
            for (int m = 0; m < 3; m++)
#pragma unroll
                for (int j = 0; j < 4; j++) {
                    int k = h * 256 + 16 * q + 4 * m + j;
                    wreg[(q * 3 + m) * 4 + j] = W[(size_t)k * DD + gj];
                }

        const float4* __restrict__ wq4 =
            (const float4*)(Wt + (h * 128 + col) * WT_STRIDE);
        const float* __restrict__ xp = x + ((size_t)b * DD + gj) * TT;
        float* __restrict__ rp = g_resbuf + ((size_t)b * DD + gj) * TT;

        const uint32_t feats_u32 = smem_u32(feats);
        const uint32_t dst_b0 = feats_u32 + (uint32_t)gj * 4u;
        const uint32_t dst_b1 = dst_b0 + (uint32_t)DD * 4u;
        const uint32_t ra = (uint32_t)(2 * h), rb_ = ra + 1u;
        const uint32_t d0a = mapa_cluster(dst_b0, ra);
        const uint32_t d0b = mapa_cluster(dst_b0, rb_);
        const uint32_t d1a = mapa_cluster(dst_b1, ra);
        const uint32_t d1b = mapa_cluster(dst_b1, rb_);

        float xv_next = __ldg(xp);

        __syncthreads();
        cluster_sync_();

        for (int t = 0; t < TT; t++) {
            if (t) cluster_wait_();
            const float xv = xv_next;

            const float4* __restrict__ f4 =
                (const float4*)(feats + (t & 1) * DD) + h * 64;
            float a = 0.f;
#pragma unroll
            for (int q = 0; q < 16; q++) {
#pragma unroll
                for (int m = 0; m < 3; m++) {
                    const float4 f = f4[4 * q + m];
                    const int wb = (q * 3 + m) * 4;
                    a = fmaf(f.x, wreg[wb + 0], a);
                    a = fmaf(f.y, wreg[wb + 1], a);
                    a = fmaf(f.z, wreg[wb + 2], a);
                    a = fmaf(f.w, wreg[wb + 3], a);
                }
                const float4 f = f4[4 * q + 3];
                const float4 w = wq4[q];
                a = fmaf(f.x, w.x, a);
                a = fmaf(f.y, w.y, a);
                a = fmaf(f.z, w.z, a);
                a = fmaf(f.w, w.w, a);
            }

            if (h == 0) redA[col] = a; else redB[col] = a;
            __syncthreads();

            // publish progress (rp[0..t-1] are visible after the barrier)
            if ((t & 127) == 0 && t != 0 && tid == 0) {
                __threadfence();
                *(volatile int*)&g_prog[(b << 2) | rank] = t;
            }

            const float s = redA[col] + redB[col];   // h0 + h1 (exact order)
            const float v = fminf(1.f, fmaxf(-1.f, 4.f * (s + xv)));

            if (t < TT - 1) {
                if ((t & 1) == 0) {
                    st_cluster_pre(d1a, v);
                    st_cluster_pre(d1b, v);
                } else {
                    st_cluster_pre(d0a, v);
                    st_cluster_pre(d0b, v);
                }
                cluster_arrive_();
                if (h == 0) rp[t] = v;
                xv_next = __ldg(xp + t + 1);
            } else {
                if (h == 0) rp[t] = v;
            }
        }

        __syncthreads();
        if (tid == 0) {
            __threadfence();
            *(volatile int*)&g_prog[(b << 2) | rank] = TT;
        }
        cluster_sync_();   // peers done with this CTA's smem; safe to reuse
    }

    // ---------------- projection work queue (all CTAs) ----------------
    __shared__ unsigned s_id;
    for (;;) {
        __syncthreads();
        if (tid == 0) s_id = atomicAdd(&g_ticket, 1u);
        __syncthreads();
        const unsigned id = s_id;
        if (id >= NTILES) break;

        const int tt = (int)(id >> 6);
        const int rem = (int)(id & 63u);
        const int b  = rem >> 2;
        const int oo = rem & 3;
        const int need = (tt + 1) * 128;

        if (tid == 0) {
#pragma unroll
            for (int r = 0; r < 4; r++)
                while (ld_acq(&g_prog[(b << 2) | r]) < need) __nanosleep(256);
        }
        __syncthreads();

        proj_tile(sm, b, oo * 128, tt * 128, lin_w, lin_b, out);
    }
}

extern "C" void kernel_launch(void* const* d_in, const int* in_sizes, int n_in,
                              void* d_out, int out_size) {
    const float* x     = (const float*)d_in[0];
    const float* W     = (const float*)d_in[1];
    const float* lin_w = (const float*)d_in[2];
    const float* lin_b = (const float*)d_in[3];
    float* out = (float*)d_out;

    cudaFuncSetAttribute(fused_kernel,
                         cudaFuncAttributeMaxDynamicSharedMemorySize,
                         SMEM_REC_BYTES);
    init_kernel<<<1, 64>>>();
    fused_kernel<<<dim3(NGRID), TPC, SMEM_REC_BYTES>>>(x, W, lin_w, lin_b, out);
}

// round 16
// speedup vs baseline: 1.4984x; 1.1788x over previous
#include <cuda_runtime.h>
#include <cstdint>

#define BB 16
#define DD 512
#define TT 4096

// merged grid: 36 clusters x 4 CTAs = 144 CTAs, 256 threads each.
#define CLU 4
#define TPC 256
#define CPC 128
#define NREC 64
#define NGRID 144
#define NTILES 2048

// rec smem layout (float offsets)
#define MB_OFF   0                         // 2 x u64 mbarriers (parity 0/1)
#define REDA_OFF 8
#define REDB_OFF 136
#define FEAT_OFF 264                       // [2][512], 16B aligned
#define WT_OFF   (FEAT_OFF + 2 * DD)       // 1288, 16B aligned
#define WT_STRIDE 68
#define SMEM_REC_FLOATS (WT_OFF + 256 * WT_STRIDE)
#define SMEM_REC_BYTES (SMEM_REC_FLOATS * 4)

#define TX_BYTES 2048u                     // 512 floats per rank per phase

__device__ float    g_resbuf[(size_t)BB * DD * TT];
__device__ int      g_prog[BB * CLU];
__device__ unsigned g_ticket;

__global__ void init_kernel() {
    int i = threadIdx.x;
    if (i < BB * CLU) g_prog[i] = 0;
    if (i == 0) g_ticket = 0u;
}

__device__ __forceinline__ uint32_t smem_u32(const void* p) {
    uint32_t a;
    asm("{ .reg .u64 t; cvta.to.shared.u64 t, %1; cvt.u32.u64 %0, t; }" : "=r"(a) : "l"(p));
    return a;
}
__device__ __forceinline__ uint32_t mapa_cluster(uint32_t addr, uint32_t rank) {
    uint32_t r;
    asm("mapa.shared::cluster.u32 %0, %1, %2;" : "=r"(r) : "r"(addr), "r"(rank));
    return r;
}
__device__ __forceinline__ void mbar_init(uint32_t addr, uint32_t cnt) {
    asm volatile("mbarrier.init.shared.b64 [%0], %1;" :: "r"(addr), "r"(cnt) : "memory");
}
__device__ __forceinline__ void mbar_arm(uint32_t addr, uint32_t bytes) {
    asm volatile("mbarrier.arrive.expect_tx.shared.b64 _, [%0], %1;"
                 :: "r"(addr), "r"(bytes) : "memory");
}
__device__ __forceinline__ void mbar_wait_parity(uint32_t addr, uint32_t parity) {
    asm volatile(
        "{ .reg .pred P;\n\t"
        "WL_%=: mbarrier.try_wait.parity.acquire.cluster.shared::cta.b64 P, [%0], %1, 0x989680;\n\t"
        "@P bra WD_%=;\n\t"
        "bra WL_%=;\n\t"
        "WD_%=: }"
        :: "r"(addr), "r"(parity) : "memory");
}
// data store that carries its tx-count to the destination CTA's mbarrier
__device__ __forceinline__ void st_async_v4(uint32_t dst, uint32_t mbar,
                                            float a, float b, float c, float d) {
    asm volatile(
        "st.async.shared::cluster.mbarrier::complete_tx::bytes.v4.b32 "
        "[%0], {%1,%2,%3,%4}, [%5];"
        :: "r"(dst), "r"(__float_as_uint(a)), "r"(__float_as_uint(b)),
           "r"(__float_as_uint(c)), "r"(__float_as_uint(d)), "r"(mbar)
        : "memory");
}
__device__ __forceinline__ void cluster_sync_() {
    asm volatile("barrier.cluster.arrive.aligned;" ::: "memory");
    asm volatile("barrier.cluster.wait.aligned;" ::: "memory");
}
__device__ __forceinline__ int ld_acq(const int* p) {
    int v;
    asm volatile("ld.acquire.gpu.global.s32 %0, [%1];" : "=r"(v) : "l"(p) : "memory");
    return v;
}

typedef unsigned long long u64;
#define FMA2(d, a, bv) \
    asm("fma.rn.f32x2 %0, %1, %2, %0;" : "+l"(d) : "l"(a), "l"(bv))
#define PACK2(o, lo, hi) \
    asm("mov.b64 %0, {%1, %2};" : "=l"(o) : "f"(lo), "f"(hi))
#define UNPACK2(lo, hi, v) \
    asm("mov.b64 {%0, %1}, %2;" : "=f"(lo), "=f"(hi) : "l"(v))

// ============================================================================
// Projection tile (identical math to R14/R15 -> bit-identical output)
// ============================================================================
__device__ void proj_tile(float* sm, int b, int o0, int t0,
                          const float* __restrict__ lin_w,
                          const float* __restrict__ lin_b,
                          float* __restrict__ out) {
    float* As = sm;
    float* Bs = sm + 1024;
    const float* rb = g_resbuf;

    const int tid = threadIdx.x;
    const int tx  = tid & 15;
    const int ty  = tid >> 4;

    u64 acc2[8][4];
#pragma unroll
    for (int r = 0; r < 8; r++)
#pragma unroll
        for (int c = 0; c < 4; c++) acc2[r][c] = 0ull;

    const int lo   = tid >> 1;
    const int half = (tid & 1) * 4;
    const int brow = tid >> 5;
    const int bc4  = (tid & 31) * 4;

    for (int k0 = 0; k0 < DD; k0 += 8) {
        float4 av = *(const float4*)&lin_w[(size_t)(o0 + lo) * DD + k0 + half];
        float4 bv = *(const float4*)&rb[((size_t)b * DD + k0 + brow) * TT + t0 + bc4];
        __syncthreads();
        As[(half + 0) * 128 + lo] = av.x; As[(half + 1) * 128 + lo] = av.y;
        As[(half + 2) * 128 + lo] = av.z; As[(half + 3) * 128 + lo] = av.w;
        *(float4*)&Bs[brow * 128 + bc4] = bv;
        __syncthreads();

#pragma unroll
        for (int ii = 0; ii < 8; ii++) {
            float4 a0 = *(const float4*)&As[ii * 128 + ty * 4];
            float4 a1 = *(const float4*)&As[ii * 128 + 64 + ty * 4];
            float4 b0 = *(const float4*)&Bs[ii * 128 + tx * 4];
            float4 b1 = *(const float4*)&Bs[ii * 128 + 64 + tx * 4];
            u64 b2[4];
            PACK2(b2[0], b0.x, b0.y); PACK2(b2[1], b0.z, b0.w);
            PACK2(b2[2], b1.x, b1.y); PACK2(b2[3], b1.z, b1.w);
            float a[8] = {a0.x, a0.y, a0.z, a0.w, a1.x, a1.y, a1.z, a1.w};
#pragma unroll
            for (int r = 0; r < 8; r++) {
                u64 a2;
                PACK2(a2, a[r], a[r]);
                FMA2(acc2[r][0], a2, b2[0]);
                FMA2(acc2[r][1], a2, b2[1]);
                FMA2(acc2[r][2], a2, b2[2]);
                FMA2(acc2[r][3], a2, b2[3]);
            }
        }
    }

#pragma unroll
    for (int g = 0; g < 2; g++) {
#pragma unroll
        for (int r = 0; r < 4; r++) {
            const int ar = g * 4 + r;
            const int o  = o0 + g * 64 + ty * 4 + r;
            const float bias = lin_b[o];
            float c0, c1, c2, c3, c4, c5, c6, c7;
            UNPACK2(c0, c1, acc2[ar][0]); UNPACK2(c2, c3, acc2[ar][1]);
            UNPACK2(c4, c5, acc2[ar][2]); UNPACK2(c6, c7, acc2[ar][3]);
            float4 v0, v1;
            v0.x = c0 + bias; v0.y = c1 + bias; v0.z = c2 + bias; v0.w = c3 + bias;
            v1.x = c4 + bias; v1.y = c5 + bias; v1.z = c6 + bias; v1.w = c7 + bias;
            float* op = &out[((size_t)b * DD + o) * TT + t0];
            *(float4*)(op + tx * 4)      = v0;
            *(float4*)(op + 64 + tx * 4) = v1;
        }
    }
}

// ============================================================================
// Fused kernel. Rec = R15 compute exactly (ordering "C", bit-exact); sync
// replaced by st.async + complete_tx + local try_wait (NO remote arrives,
// NO barrier.cluster in the loop). Values packed into v4 stores via 3
// lane shuffles (quad lanes hold consecutive columns) -> 128 tx/rank/phase.
// ============================================================================
__global__ void __cluster_dims__(CLU, 1, 1) __launch_bounds__(TPC, 1)
fused_kernel(const float* __restrict__ x, const float* __restrict__ W,
             const float* __restrict__ lin_w, const float* __restrict__ lin_b,
             float* __restrict__ out) {
    extern __shared__ float sm[];
    const int tid = threadIdx.x;
    const int bid = blockIdx.x;

    if (bid < NREC) {
        float* redA  = sm + REDA_OFF;
        float* redB  = sm + REDB_OFF;
        float* feats = sm + FEAT_OFF;
        float* Wt    = sm + WT_OFF;

        const int rank = bid & 3;
        const int b    = bid >> 2;
        const int col  = tid & 127;
        const int h    = tid >> 7;
        const int j0   = rank * CPC;
        const int gj   = j0 + col;

        const uint32_t sm_u32 = smem_u32(sm);
        const uint32_t mb_base = sm_u32 + MB_OFF * 4;   // mbar[p] at +8p

        if (tid == 0) {
            mbar_init(mb_base, 1);
            mbar_init(mb_base + 8, 1);
            mbar_arm(mb_base, TX_BYTES);       // phase for wait at t=2
            mbar_arm(mb_base + 8, TX_BYTES);   // phase for wait at t=1
            asm volatile("fence.mbarrier_init.release.cluster;" ::: "memory");
        }

        for (int e = tid; e < 256 * 64; e += TPC) {
            int colr = e & 127;
            int j    = (e >> 7) & 3;
            int q    = (e >> 9) & 15;
            int hr   = e >> 13;
            int k    = hr * 256 + 16 * q + 12 + j;
            Wt[(hr * 128 + colr) * WT_STRIDE + q * 4 + j] =
                W[(size_t)k * DD + j0 + colr];
        }
        for (int e = tid; e < 2 * DD; e += TPC) feats[e] = 0.f;

        float wreg[192];
#pragma unroll
        for (int q = 0; q < 16; q++)
#pragma unroll
            for (int m = 0; m < 3; m++)
#pragma unroll
                for (int j = 0; j < 4; j++) {
                    int k = h * 256 + 16 * q + 4 * m + j;
                    wreg[(q * 3 + m) * 4 + j] = W[(size_t)k * DD + gj];
                }

        const float4* __restrict__ wq4 =
            (const float4*)(Wt + (h * 128 + col) * WT_STRIDE);
        const float* __restrict__ xp = x + ((size_t)b * DD + gj) * TT;
        float* __restrict__ rp = g_resbuf + ((size_t)b * DD + gj) * TT;

        // hoisted mapped addresses: data quad base + mbar, for 2 duty ranks
        const uint32_t feats_u32 = sm_u32 + FEAT_OFF * 4;
        const uint32_t quad = (uint32_t)(gj & ~3);
        const uint32_t ra = (uint32_t)(2 * h), rb_ = ra + 1u;
        const uint32_t d0a = mapa_cluster(feats_u32 + quad * 4u, ra);
        const uint32_t d0b = mapa_cluster(feats_u32 + quad * 4u, rb_);
        const uint32_t m0a = mapa_cluster(mb_base, ra);
        const uint32_t m0b = mapa_cluster(mb_base, rb_);

        float xv_next = __ldg(xp);
        int ph0 = 0, ph1 = 0;

        __syncthreads();
        cluster_sync_();   // mbar init/arm + feats zero visible cluster-wide

        for (int t = 0; t < TT; t++) {
            if (t) {
                const int p = t & 1;
                const uint32_t mb = mb_base + (uint32_t)p * 8u;
                if (p) { mbar_wait_parity(mb, (uint32_t)ph1); ph1 ^= 1; }
                else   { mbar_wait_parity(mb, (uint32_t)ph0); ph0 ^= 1; }
                if (tid == 0) mbar_arm(mb, TX_BYTES);  // next phase of this mbar
            }
            const float xv = xv_next;

            const float4* __restrict__ f4 =
                (const float4*)(feats + (t & 1) * DD) + h * 64;
            float a = 0.f;
#pragma unroll
            for (int q = 0; q < 16; q++) {
#pragma unroll
                for (int m = 0; m < 3; m++) {
                    const float4 f = f4[4 * q + m];
                    const int wb = (q * 3 + m) * 4;
                    a = fmaf(f.x, wreg[wb + 0], a);
                    a = fmaf(f.y, wreg[wb + 1], a);
                    a = fmaf(f.z, wreg[wb + 2], a);
                    a = fmaf(f.w, wreg[wb + 3], a);
                }
                const float4 f = f4[4 * q + 3];
                const float4 w = wq4[q];
                a = fmaf(f.x, w.x, a);
                a = fmaf(f.y, w.y, a);
                a = fmaf(f.z, w.z, a);
                a = fmaf(f.w, w.w, a);
            }

            if (h == 0) redA[col] = a; else redB[col] = a;
            __syncthreads();

            if ((t & 127) == 0 && t != 0 && tid == 0) {
                __threadfence();
                *(volatile int*)&g_prog[(b << 2) | rank] = t;
            }

            const float s = redA[col] + redB[col];   // h0 + h1 (exact order)
            const float v = fminf(1.f, fmaxf(-1.f, 4.f * (s + xv)));

            if (t < TT - 1) {
                // pack quad (lanes hold consecutive columns) and push with tx
                const float v1 = __shfl_down_sync(0xffffffffu, v, 1);
                const float v2 = __shfl_down_sync(0xffffffffu, v, 2);
                const float v3 = __shfl_down_sync(0xffffffffu, v, 3);
                if ((tid & 3) == 0) {
                    const uint32_t pn   = (uint32_t)((t & 1) ^ 1);
                    const uint32_t doff = pn * (uint32_t)(DD * 4);
                    const uint32_t moff = pn * 8u;
                    st_async_v4(d0a + doff, m0a + moff, v, v1, v2, v3);
                    st_async_v4(d0b + doff, m0b + moff, v, v1, v2, v3);
                }
                if (h == 0) rp[t] = v;
                xv_next = __ldg(xp + t + 1);
            } else {
                if (h == 0) rp[t] = v;
            }
        }

        __syncthreads();
        if (tid == 0) {
            __threadfence();
            *(volatile int*)&g_prog[(b << 2) | rank] = TT;
        }
        cluster_sync_();   // teardown: keep smem alive until all ranks done
    }

    // ---------------- projection work queue (all CTAs) ----------------
    __shared__ unsigned s_id;
    for (;;) {
        __syncthreads();
        if (tid == 0) s_id = atomicAdd(&g_ticket, 1u);
        __syncthreads();
        const unsigned id = s_id;
        if (id >= NTILES) break;

        const int tt = (int)(id >> 6);
        const int rem = (int)(id & 63u);
        const int b  = rem >> 2;
        const int oo = rem & 3;
        const int need = (tt + 1) * 128;

        if (tid == 0) {
#pragma unroll
            for (int r = 0; r < 4; r++)
                while (ld_acq(&g_prog[(b << 2) | r]) < need) __nanosleep(256);
        }
        __syncthreads();

        proj_tile(sm, b, oo * 128, tt * 128, lin_w, lin_b, out);
    }
}

extern "C" void kernel_launch(void* const* d_in, const int* in_sizes, int n_in,
                              void* d_out, int out_size) {
    const float* x     = (const float*)d_in[0];
    const float* W     = (const float*)d_in[1];
    const float* lin_w = (const float*)d_in[2];
    const float* lin_b = (const float*)d_in[3];
    float* out = (float*)d_out;

    cudaFuncSetAttribute(fused_kernel,
                         cudaFuncAttributeMaxDynamicSharedMemorySize,
                         SMEM_REC_BYTES);
    init_kernel<<<1, 64>>>();
    fused_kernel<<<dim3(NGRID), TPC, SMEM_REC_BYTES>>>(x, W, lin_w, lin_b, out);
}